// round 12
// baseline (speedup 1.0000x reference)
#include <cuda_runtime.h>
#include <cuda_bf16.h>
#include <cstdint>

// Problem constants
#define BATCH 8
#define CDIM  128
#define NPOS  2304              // H*W = 48*48
#define TM    256               // CTA tile M (y rows)
#define TN    128               // CTA tile N (x cols)
#define NL    3                 // n-tiles per CTA (A reused across them)
#define MT_M  (NPOS / TM)       // 9
#define MT_NS (NPOS / (TN*NL))  // 6 n-strips
#define SW    68                // SMEM row stride in 32-bit words (64 + 4 pad)
#define NTHREADS 512

// ---------------------------------------------------------------------------
// Scratch for squared norms (device globals — no allocation in kernel_launch)
// ---------------------------------------------------------------------------
__device__ float g_sx[BATCH * NPOS];
__device__ float g_sy[BATCH * NPOS];

// ---------------------------------------------------------------------------
// Kernel 1: per-position squared norms   sx[b,n] = sum_c x[b,c,n]^2  (fp32 exact)
// ---------------------------------------------------------------------------
__global__ void pwd_norms_kernel(const float* __restrict__ x,
                                 const float* __restrict__ y) {
    int idx = blockIdx.x * blockDim.x + threadIdx.x;
    if (idx >= BATCH * NPOS) return;
    int b = idx / NPOS;
    int n = idx - b * NPOS;
    const float* xp = x + (size_t)b * CDIM * NPOS + n;
    const float* yp = y + (size_t)b * CDIM * NPOS + n;
    float sx = 0.f, sy = 0.f;
#pragma unroll 8
    for (int c = 0; c < CDIM; c++) {
        float xv = xp[(size_t)c * NPOS];
        float yv = yp[(size_t)c * NPOS];
        sx = fmaf(xv, xv, sx);
        sy = fmaf(yv, yv, sy);
    }
    g_sx[idx] = sx;
    g_sy[idx] = sy;
}

// ---------------------------------------------------------------------------
// bf16 warp MMA (sm_80+ PTX): D(16x8,f32) += A(16x16,bf16) * B(16x8,bf16)
// ---------------------------------------------------------------------------
__device__ __forceinline__ void mma_bf16(
    float& d0, float& d1, float& d2, float& d3,
    uint32_t a0, uint32_t a1, uint32_t a2, uint32_t a3,
    uint32_t b0, uint32_t b1)
{
    asm volatile(
        "mma.sync.aligned.m16n8k16.row.col.f32.bf16.bf16.f32 "
        "{%0,%1,%2,%3}, {%4,%5,%6,%7}, {%8,%9}, {%0,%1,%2,%3};"
        : "+f"(d0), "+f"(d1), "+f"(d2), "+f"(d3)
        : "r"(a0), "r"(a1), "r"(a2), "r"(a3), "r"(b0), "r"(b1));
}

__device__ __forceinline__ uint32_t pack_bf16x2(float lo, float hi) {
    __nv_bfloat162 p = __floats2bfloat162_rn(lo, hi);   // .x = lo (lower k)
    return *reinterpret_cast<uint32_t*>(&p);
}

// ---------------------------------------------------------------------------
// Kernel 2: bf16 mma.sync GEMM, CTA 256x128, A reused over NL=3 n-tiles,
// B staging for tile t+1 software-pipelined into tile t's mainloop
// (double-buffered sB, 4-slot syCol ring).
//   out[b,i,j] = sx[i] + sy[j] - 2 * (y_i . x_j)
// ---------------------------------------------------------------------------
__global__ __launch_bounds__(NTHREADS, 1)
void pwd_gemm_kernel(const float* __restrict__ x,
                     const float* __restrict__ y,
                     float* __restrict__ out) {
    extern __shared__ uint32_t dsm[];
    uint32_t* sA  = dsm;                       // 256 * 68 words
    uint32_t* sB0 = dsm + TM * SW;             // 128 * 68 words
    uint32_t* sB1 = sB0 + TN * SW;             // 128 * 68 words
    float* s_sxRow = (float*)(sB1 + TN * SW);  // 256 floats
    float* s_syCol = s_sxRow + TM;             // 4 * 128 floats (ring)

    int tid  = threadIdx.x;
    int lane = tid & 31;
    int w    = tid >> 5;
    int qid  = lane >> 2;   // 0..7
    int qtr  = lane & 3;    // 0..3
    int wm   = w >> 2;      // warp row 0..3 (64 rows each)
    int wn   = w & 3;       // warp col 0..3 (32 cols each)

    int m0     = blockIdx.y * TM;
    int nbase0 = blockIdx.x * (NL * TN);
    int b      = blockIdx.z;
    size_t bOff = (size_t)b * CDIM * NPOS;

    const float* yb = y + bOff + m0;

    // lane map for staging: plo = tid&7 (pos low), klo = (tid>>3)&3 (kp low)
    int plo = tid & 7;
    int klo = (tid >> 3) & 3;
    int w5  = tid >> 5;             // 0..15
    int nst = w5 * 8 + plo;         // this thread's fixed B staging row 0..127

    // ---- prologue: stage A (once), sxRow, B tile 0, syCol slot 0 ----
#pragma unroll
    for (int i = 0; i < 32; i++) {
        int m  = plo + 8 * w5 + 128 * (i & 1);   // 0..255
        int kp = klo + 4 * (i >> 1);             // 0..63
        float f0 = yb[(size_t)(2 * kp) * NPOS + m];
        float f1 = yb[(size_t)(2 * kp + 1) * NPOS + m];
        sA[m * SW + kp] = pack_bf16x2(f0, f1);
    }
    {
        const float* x0 = x + bOff + nbase0;
#pragma unroll
        for (int i = 0; i < 16; i++) {
            int kp = klo + 4 * i;
            float f0 = x0[(size_t)(2 * kp) * NPOS + nst];
            float f1 = x0[(size_t)(2 * kp + 1) * NPOS + nst];
            sB0[nst * SW + kp] = pack_bf16x2(f0, f1);
        }
    }
    if (tid < TM) {
        s_sxRow[tid] = g_sx[b * NPOS + m0 + tid];
    } else if (tid < TM + TN) {
        s_syCol[tid - TM] = g_sy[b * NPOS + nbase0 + (tid - TM)];
    }
    __syncthreads();

    const uint32_t* pA = sA + (wm * 64 + qid) * SW + qtr;

    // ---- tile loop (rolled) ----
    for (int t = 0; t < NL; t++) {
        int n0 = nbase0 + t * TN;
        uint32_t* sBc = (t & 1) ? sB1 : sB0;
        uint32_t* sBn = (t & 1) ? sB0 : sB1;
        const uint32_t* pB = sBc + (wn * 32 + qid) * SW + qtr;
        bool doStage = (t < NL - 1);

        // staging pointers for tile t+1 (valid only if doStage)
        const float* xn0 = x + bOff + (n0 + TN) + (size_t)(2 * klo) * NPOS + nst;
        uint32_t* sBnp = sBn + nst * SW + klo;

        // stage next tile's syCol into ring slot t+1 (distinct from slot t)
        if (doStage && tid >= TM && tid < TM + TN) {
            s_syCol[(t + 1) * TN + (tid - TM)] = g_sy[b * NPOS + (n0 + TN) + (tid - TM)];
        }

        float acc[4][4][4];
#pragma unroll
        for (int mi = 0; mi < 4; mi++)
#pragma unroll
            for (int j = 0; j < 4; j++)
#pragma unroll
                for (int r = 0; r < 4; r++) acc[mi][j][r] = 0.f;

        // main loop: 8 k-steps; 2 staging iterations pipelined into each step
#pragma unroll
        for (int s = 0; s < 8; s++) {
            // staging LDGs issued first (consumed at end of step)
            float f0, f1, f2, f3;
            if (doStage) {
                f0 = xn0[(size_t)(8 * (2 * s)) * NPOS];
                f1 = xn0[(size_t)(8 * (2 * s) + 1) * NPOS];
                f2 = xn0[(size_t)(8 * (2 * s + 1)) * NPOS];
                f3 = xn0[(size_t)(8 * (2 * s + 1) + 1) * NPOS];
            }

            // B fragments for this step (8 regs)
            uint32_t bf0[4], bf1[4];
#pragma unroll
            for (int j = 0; j < 4; j++) {
                bf0[j] = pB[j * 8 * SW + s * 8];
                bf1[j] = pB[j * 8 * SW + s * 8 + 4];
            }
            // A fragments per mi (4 live at a time)
#pragma unroll
            for (int mi = 0; mi < 4; mi++) {
                uint32_t a0 = pA[(mi * 16 + 0) * SW + s * 8];
                uint32_t a1 = pA[(mi * 16 + 8) * SW + s * 8];
                uint32_t a2 = pA[(mi * 16 + 0) * SW + s * 8 + 4];
                uint32_t a3 = pA[(mi * 16 + 8) * SW + s * 8 + 4];
#pragma unroll
                for (int j = 0; j < 4; j++) {
                    mma_bf16(acc[mi][j][0], acc[mi][j][1], acc[mi][j][2], acc[mi][j][3],
                             a0, a1, a2, a3, bf0[j], bf1[j]);
                }
            }

            // staging STS at end of step (LDG latency hidden by compute above)
            if (doStage) {
                sBnp[4 * (2 * s)]     = pack_bf16x2(f0, f1);
                sBnp[4 * (2 * s + 1)] = pack_bf16x2(f2, f3);
            }
        }
        __syncthreads();   // B(t+1) staged + all reads of sBc done

        // fused epilogue: P = sx[i] + sy[j] - 2*acc, float2 stores.
        // Reads only acc/s_sxRow/syCol slot t — no sync needed after
        // (next tile stages into different buffers/slots).
        const float* syCur = s_syCol + t * TN;
#pragma unroll
        for (int mi = 0; mi < 4; mi++) {
#pragma unroll
            for (int h = 0; h < 2; h++) {
                int r = wm * 64 + mi * 16 + h * 8 + qid;
                float sxv = s_sxRow[r];
                size_t rowOff = ((size_t)b * NPOS + m0 + r) * (size_t)NPOS + n0;
#pragma unroll
                for (int j = 0; j < 4; j++) {
                    int cb = wn * 32 + 8 * j + 2 * qtr;
                    float d0 = acc[mi][j][h * 2 + 0];
                    float d1 = acc[mi][j][h * 2 + 1];
                    float2 v;
                    v.x = syCur[cb + 0] + fmaf(-2.f, d0, sxv);
                    v.y = syCur[cb + 1] + fmaf(-2.f, d1, sxv);
                    *reinterpret_cast<float2*>(out + rowOff + cb) = v;
                }
            }
        }
    }
}

// ---------------------------------------------------------------------------
// Launch
// ---------------------------------------------------------------------------
extern "C" void kernel_launch(void* const* d_in, const int* in_sizes, int n_in,
                              void* d_out, int out_size) {
    const float* x = (const float*)d_in[0];
    const float* y = (const float*)d_in[1];
    float* out = (float*)d_out;

    // Kernel 1: squared norms
    int total = BATCH * NPOS;
    pwd_norms_kernel<<<(total + 255) / 256, 256>>>(x, y);

    // Kernel 2: tiled bf16 GEMM + fused epilogue, pipelined B staging
    int smemBytes = (TM * SW + 2 * TN * SW + TM + 4 * TN) * 4;   // ~142 KB
    cudaFuncSetAttribute(pwd_gemm_kernel,
                         cudaFuncAttributeMaxDynamicSharedMemorySize, smemBytes);
    dim3 grid(MT_NS, MT_M, BATCH);
    pwd_gemm_kernel<<<grid, NTHREADS, smemBytes>>>(x, y, out);
}

// round 13
// speedup vs baseline: 1.1628x; 1.1628x over previous
#include <cuda_runtime.h>
#include <cuda_bf16.h>
#include <cstdint>

// Problem constants
#define BATCH 8
#define CDIM  128
#define NPOS  2304              // H*W = 48*48
#define TM    256               // CTA tile M (y rows)
#define TN    128               // CTA tile N (x cols)
#define NL    3                 // n-tiles per CTA (A reused across them)
#define MT_M  (NPOS / TM)       // 9
#define MT_NS (NPOS / (TN*NL))  // 6 n-strips
#define SW    68                // SMEM row stride in 32-bit words (64 + 4 pad)
#define NTHREADS 512
#define KPW   64                // bf16x2 words per position row (CDIM/2)

// ---------------------------------------------------------------------------
// Scratch: squared norms + pre-converted bf16 transposed copies
// g_xbf/g_ybf layout: [b][pos][kp]  (row = 64 uint32 = 256 B, 16B-aligned)
// ---------------------------------------------------------------------------
__device__ float g_sx[BATCH * NPOS];
__device__ float g_sy[BATCH * NPOS];
__device__ uint4 g_xbf[BATCH * NPOS * (KPW / 4)];
__device__ uint4 g_ybf[BATCH * NPOS * (KPW / 4)];

__device__ __forceinline__ uint32_t pack_bf16x2(float lo, float hi) {
    __nv_bfloat162 p = __floats2bfloat162_rn(lo, hi);   // .x = lo (lower k)
    return *reinterpret_cast<uint32_t*>(&p);
}

// ---------------------------------------------------------------------------
// Kernel 1: norms (fp32 exact) + bf16 transpose-convert
// ---------------------------------------------------------------------------
__global__ void pwd_norms_kernel(const float* __restrict__ x,
                                 const float* __restrict__ y) {
    int idx = blockIdx.x * blockDim.x + threadIdx.x;
    if (idx >= BATCH * NPOS) return;
    int b = idx / NPOS;
    int n = idx - b * NPOS;
    const float* xp = x + (size_t)b * CDIM * NPOS + n;
    const float* yp = y + (size_t)b * CDIM * NPOS + n;
    uint32_t* xw = reinterpret_cast<uint32_t*>(g_xbf) + (size_t)idx * KPW;
    uint32_t* yw = reinterpret_cast<uint32_t*>(g_ybf) + (size_t)idx * KPW;
    float sx = 0.f, sy = 0.f;
#pragma unroll 8
    for (int kp = 0; kp < KPW; kp++) {
        float x0 = xp[(size_t)(2 * kp) * NPOS];
        float x1 = xp[(size_t)(2 * kp + 1) * NPOS];
        float y0 = yp[(size_t)(2 * kp) * NPOS];
        float y1 = yp[(size_t)(2 * kp + 1) * NPOS];
        sx = fmaf(x0, x0, fmaf(x1, x1, sx));
        sy = fmaf(y0, y0, fmaf(y1, y1, sy));
        xw[kp] = pack_bf16x2(x0, x1);
        yw[kp] = pack_bf16x2(y0, y1);
    }
    g_sx[idx] = sx;
    g_sy[idx] = sy;
}

// ---------------------------------------------------------------------------
// PTX helpers
// ---------------------------------------------------------------------------
__device__ __forceinline__ uint32_t smem_to_u32(const void* smem_ptr) {
    uint32_t addr;
    asm("{ .reg .u64 tmp; cvta.to.shared.u64 tmp, %1; cvt.u32.u64 %0, tmp; }"
        : "=r"(addr) : "l"(smem_ptr));
    return addr;
}

__device__ __forceinline__ void cp_async16(uint32_t smem_addr, const void* gmem) {
    asm volatile("cp.async.cg.shared.global [%0], [%1], 16;"
                 :: "r"(smem_addr), "l"(gmem));
}
#define CP_ASYNC_COMMIT() asm volatile("cp.async.commit_group;")
#define CP_ASYNC_WAIT_ALL() asm volatile("cp.async.wait_group 0;" ::: "memory")

__device__ __forceinline__ void mma_bf16(
    float& d0, float& d1, float& d2, float& d3,
    uint32_t a0, uint32_t a1, uint32_t a2, uint32_t a3,
    uint32_t b0, uint32_t b1)
{
    asm volatile(
        "mma.sync.aligned.m16n8k16.row.col.f32.bf16.bf16.f32 "
        "{%0,%1,%2,%3}, {%4,%5,%6,%7}, {%8,%9}, {%0,%1,%2,%3};"
        : "+f"(d0), "+f"(d1), "+f"(d2), "+f"(d3)
        : "r"(a0), "r"(a1), "r"(a2), "r"(a3), "r"(b0), "r"(b1));
}

// ---------------------------------------------------------------------------
// Kernel 2: bf16 mma.sync GEMM, CTA 256x128, A reused over NL=3 n-tiles,
// all staging via cp.async from pre-converted bf16 (register-free, async).
//   out[b,i,j] = sx[i] + sy[j] - 2 * (y_i . x_j)
// ---------------------------------------------------------------------------
__global__ __launch_bounds__(NTHREADS, 1)
void pwd_gemm_kernel(float* __restrict__ out) {
    extern __shared__ uint32_t dsm[];
    uint32_t* sA  = dsm;                       // 256 * 68 words
    uint32_t* sB0 = dsm + TM * SW;             // 128 * 68 words
    uint32_t* sB1 = sB0 + TN * SW;             // 128 * 68 words
    float* s_sxRow = (float*)(sB1 + TN * SW);  // 256 floats
    float* s_syCol = s_sxRow + TM;             // 3 * 128 floats (ring)
    uint32_t smu = smem_to_u32(dsm);

    int tid  = threadIdx.x;
    int lane = tid & 31;
    int w    = tid >> 5;
    int qid  = lane >> 2;   // 0..7
    int qtr  = lane & 3;    // 0..3
    int wm   = w >> 2;      // warp row 0..3 (64 rows each)
    int wn   = w & 3;       // warp col 0..3 (32 cols each)

    int m0     = blockIdx.y * TM;
    int nbase0 = blockIdx.x * (NL * TN);
    int b      = blockIdx.z;

    // chunk map: c16 = chunk col (16B units, 0..15), rq = row quotient
    int c16 = tid & 15;
    int rq  = tid >> 4;     // 0..31

    const uint4* ybf = g_ybf + ((size_t)b * NPOS + m0) * (KPW / 4);
    const uint4* xbf0 = g_xbf + ((size_t)b * NPOS + nbase0) * (KPW / 4);

    // ---- prologue: async-stage A (8 chunks/thr) + B tile 0 (4 chunks/thr) ----
#pragma unroll
    for (int i = 0; i < 8; i++) {
        int m = i * 32 + rq;   // 0..255
        cp_async16(smu + (uint32_t)(m * SW + c16 * 4) * 4, ybf + m * 16 + c16);
    }
    uint32_t sB0u = smu + (uint32_t)(TM * SW) * 4;
    uint32_t sB1u = sB0u + (uint32_t)(TN * SW) * 4;
#pragma unroll
    for (int i = 0; i < 4; i++) {
        int n = i * 32 + rq;   // 0..127
        cp_async16(sB0u + (uint32_t)(n * SW + c16 * 4) * 4, xbf0 + n * 16 + c16);
    }
    CP_ASYNC_COMMIT();

    if (tid < TM) {
        s_sxRow[tid] = g_sx[b * NPOS + m0 + tid];
    } else if (tid < TM + TN) {
        s_syCol[tid - TM] = g_sy[b * NPOS + nbase0 + (tid - TM)];
    }
    CP_ASYNC_WAIT_ALL();
    __syncthreads();

    const uint32_t* pA = sA + (wm * 64 + qid) * SW + qtr;

    // ---- tile loop ----
    for (int t = 0; t < NL; t++) {
        int n0 = nbase0 + t * TN;
        const uint32_t* pB = ((t & 1) ? sB1 : sB0) + (wn * 32 + qid) * SW + qtr;

        // issue next tile's B staging (register-free) + syCol slot t+1
        if (t < NL - 1) {
            uint32_t dstu = (t & 1) ? sB0u : sB1u;
            const uint4* xbfn = g_xbf + ((size_t)b * NPOS + n0 + TN) * (KPW / 4);
#pragma unroll
            for (int i = 0; i < 4; i++) {
                int n = i * 32 + rq;
                cp_async16(dstu + (uint32_t)(n * SW + c16 * 4) * 4, xbfn + n * 16 + c16);
            }
            CP_ASYNC_COMMIT();
            if (tid >= TM && tid < TM + TN) {
                s_syCol[(t + 1) * TN + (tid - TM)] = g_sy[b * NPOS + (n0 + TN) + (tid - TM)];
            }
        }

        float acc[4][4][4];
#pragma unroll
        for (int mi = 0; mi < 4; mi++)
#pragma unroll
            for (int j = 0; j < 4; j++)
#pragma unroll
                for (int r = 0; r < 4; r++) acc[mi][j][r] = 0.f;

        // main loop: 8 k-steps of K=16; 24 LDS + 16 MMA per step (R10 form)
#pragma unroll
        for (int s = 0; s < 8; s++) {
            uint32_t af[4][4];
#pragma unroll
            for (int mi = 0; mi < 4; mi++) {
                af[mi][0] = pA[(mi * 16 + 0) * SW + s * 8];
                af[mi][1] = pA[(mi * 16 + 8) * SW + s * 8];
                af[mi][2] = pA[(mi * 16 + 0) * SW + s * 8 + 4];
                af[mi][3] = pA[(mi * 16 + 8) * SW + s * 8 + 4];
            }
#pragma unroll
            for (int j = 0; j < 4; j++) {
                uint32_t b0 = pB[j * 8 * SW + s * 8];
                uint32_t b1 = pB[j * 8 * SW + s * 8 + 4];
#pragma unroll
                for (int mi = 0; mi < 4; mi++) {
                    mma_bf16(acc[mi][j][0], acc[mi][j][1], acc[mi][j][2], acc[mi][j][3],
                             af[mi][0], af[mi][1], af[mi][2], af[mi][3], b0, b1);
                }
            }
        }

        // fused epilogue: P = sx[i] + sy[j] - 2*acc, float2 stores
        const float* syCur = s_syCol + t * TN;
#pragma unroll
        for (int mi = 0; mi < 4; mi++) {
#pragma unroll
            for (int h = 0; h < 2; h++) {
                int r = wm * 64 + mi * 16 + h * 8 + qid;
                float sxv = s_sxRow[r];
                size_t rowOff = ((size_t)b * NPOS + m0 + r) * (size_t)NPOS + n0;
#pragma unroll
                for (int j = 0; j < 4; j++) {
                    int cb = wn * 32 + 8 * j + 2 * qtr;
                    float d0 = acc[mi][j][h * 2 + 0];
                    float d1 = acc[mi][j][h * 2 + 1];
                    float2 v;
                    v.x = syCur[cb + 0] + fmaf(-2.f, d0, sxv);
                    v.y = syCur[cb + 1] + fmaf(-2.f, d1, sxv);
                    *reinterpret_cast<float2*>(out + rowOff + cb) = v;
                }
            }
        }

        if (t < NL - 1) {
            CP_ASYNC_WAIT_ALL();   // B(t+1) landed (issued ~11 kcyc ago)
            __syncthreads();       // all warps done with sBc(t) + B(t+1) visible
        }
    }
}

// ---------------------------------------------------------------------------
// Launch
// ---------------------------------------------------------------------------
extern "C" void kernel_launch(void* const* d_in, const int* in_sizes, int n_in,
                              void* d_out, int out_size) {
    const float* x = (const float*)d_in[0];
    const float* y = (const float*)d_in[1];
    float* out = (float*)d_out;

    // Kernel 1: norms + bf16 transpose-convert
    int total = BATCH * NPOS;
    pwd_norms_kernel<<<(total + 255) / 256, 256>>>(x, y);

    // Kernel 2: tiled bf16 GEMM, cp.async staging, fused epilogue
    int smemBytes = (TM * SW + 2 * TN * SW + TM + 3 * TN) * 4;   // ~139 KB
    cudaFuncSetAttribute(pwd_gemm_kernel,
                         cudaFuncAttributeMaxDynamicSharedMemorySize, smemBytes);
    dim3 grid(MT_NS, MT_M, BATCH);
    pwd_gemm_kernel<<<grid, NTHREADS, smemBytes>>>(out);
}

// round 14
// speedup vs baseline: 1.3895x; 1.1950x over previous
#include <cuda_runtime.h>
#include <cuda_bf16.h>
#include <cstdint>

// Problem constants
#define BATCH 8
#define CDIM  128
#define NPOS  2304              // H*W = 48*48
#define TM    256               // CTA tile M (y rows)
#define TN    128               // CTA tile N (x cols)
#define NL    3                 // n-tiles per CTA (A reused across them)
#define MT_M  (NPOS / TM)       // 9
#define MT_NS (NPOS / (TN*NL))  // 6 n-strips
#define SW    68                // SMEM row stride in 32-bit words (64 + 4 pad)
#define NTHREADS 512
#define KPW   64                // bf16x2 words per position row (CDIM/2)

// ---------------------------------------------------------------------------
// Scratch: squared norms + pre-converted bf16 transposed copies
// g_xbf/g_ybf layout: [b][pos][kp]  (row = 64 uint32 = 256 B, 16B-aligned)
// ---------------------------------------------------------------------------
__device__ float g_sx[BATCH * NPOS];
__device__ float g_sy[BATCH * NPOS];
__device__ uint4 g_xbf[BATCH * NPOS * (KPW / 4)];
__device__ uint4 g_ybf[BATCH * NPOS * (KPW / 4)];

__device__ __forceinline__ uint32_t pack_bf16x2(float lo, float hi) {
    __nv_bfloat162 p = __floats2bfloat162_rn(lo, hi);   // .x = lo (lower k)
    return *reinterpret_cast<uint32_t*>(&p);
}

// ---------------------------------------------------------------------------
// Kernel 1: norms (fp32 exact) + bf16 transpose-convert, SMEM tile transpose.
// Block: 32 positions x 128 channels of x AND y. All gmem accesses coalesced.
// ---------------------------------------------------------------------------
#define TPOS 32
#define TSW  129                // fp32 SMEM stride: bank = (n + c) mod 32

__global__ __launch_bounds__(256)
void pwd_norms_kernel(const float* __restrict__ x,
                      const float* __restrict__ y) {
    __shared__ float xs[TPOS * TSW];
    __shared__ float ys[TPOS * TSW];

    int t  = threadIdx.x;
    int n0 = blockIdx.x * TPOS;
    int b  = blockIdx.y;
    size_t bOff = (size_t)b * CDIM * NPOS + n0;

    // Phase A: coalesced reads [c][n] -> SMEM [n][c]
    {
        int n = t & 31;
        int c0 = t >> 5;             // 0..7
#pragma unroll
        for (int i = 0; i < 16; i++) {
            int c = i * 8 + c0;
            xs[n * TSW + c] = x[bOff + (size_t)c * NPOS + n];
            ys[n * TSW + c] = y[bOff + (size_t)c * NPOS + n];
        }
    }
    __syncthreads();

    // Phase B: norms. 8 threads per position, 16 channels each, shfl reduce.
    {
        int n   = t >> 3;            // 0..31
        int sub = t & 7;             // 0..7
        const float* xr = xs + n * TSW + sub * 16;
        const float* yr = ys + n * TSW + sub * 16;
        float sx = 0.f, sy = 0.f;
#pragma unroll
        for (int c = 0; c < 16; c++) {
            float xv = xr[c], yv = yr[c];
            sx = fmaf(xv, xv, sx);
            sy = fmaf(yv, yv, sy);
        }
#pragma unroll
        for (int o = 4; o > 0; o >>= 1) {
            sx += __shfl_xor_sync(0xffffffffu, sx, o);
            sy += __shfl_xor_sync(0xffffffffu, sy, o);
        }
        if (sub == 0) {
            g_sx[b * NPOS + n0 + n] = sx;
            g_sy[b * NPOS + n0 + n] = sy;
        }
    }

    // Phase C: bf16 pack + coalesced writes. word w = n*64 + kp, consecutive
    // threads -> consecutive gmem words.
    {
        uint32_t* xw = reinterpret_cast<uint32_t*>(g_xbf) + ((size_t)b * NPOS + n0) * KPW;
        uint32_t* yw = reinterpret_cast<uint32_t*>(g_ybf) + ((size_t)b * NPOS + n0) * KPW;
#pragma unroll
        for (int i = 0; i < 8; i++) {
            int wd = i * 256 + t;    // 0..2047
            int n  = wd >> 6;
            int kp = wd & 63;
            const float* xr = xs + n * TSW + 2 * kp;
            const float* yr = ys + n * TSW + 2 * kp;
            xw[wd] = pack_bf16x2(xr[0], xr[1]);
            yw[wd] = pack_bf16x2(yr[0], yr[1]);
        }
    }
}

// ---------------------------------------------------------------------------
// PTX helpers
// ---------------------------------------------------------------------------
__device__ __forceinline__ uint32_t smem_to_u32(const void* smem_ptr) {
    uint32_t addr;
    asm("{ .reg .u64 tmp; cvta.to.shared.u64 tmp, %1; cvt.u32.u64 %0, tmp; }"
        : "=r"(addr) : "l"(smem_ptr));
    return addr;
}

__device__ __forceinline__ void cp_async16(uint32_t smem_addr, const void* gmem) {
    asm volatile("cp.async.cg.shared.global [%0], [%1], 16;"
                 :: "r"(smem_addr), "l"(gmem));
}
#define CP_ASYNC_COMMIT() asm volatile("cp.async.commit_group;")
#define CP_ASYNC_WAIT_ALL() asm volatile("cp.async.wait_group 0;" ::: "memory")

__device__ __forceinline__ void mma_bf16(
    float& d0, float& d1, float& d2, float& d3,
    uint32_t a0, uint32_t a1, uint32_t a2, uint32_t a3,
    uint32_t b0, uint32_t b1)
{
    asm volatile(
        "mma.sync.aligned.m16n8k16.row.col.f32.bf16.bf16.f32 "
        "{%0,%1,%2,%3}, {%4,%5,%6,%7}, {%8,%9}, {%0,%1,%2,%3};"
        : "+f"(d0), "+f"(d1), "+f"(d2), "+f"(d3)
        : "r"(a0), "r"(a1), "r"(a2), "r"(a3), "r"(b0), "r"(b1));
}

// ---------------------------------------------------------------------------
// Kernel 2: bf16 mma.sync GEMM, CTA 256x128, A reused over NL=3 n-tiles,
// all staging via cp.async from pre-converted bf16 (register-free, async).
//   out[b,i,j] = sx[i] + sy[j] - 2 * (y_i . x_j)
// (unchanged from R12)
// ---------------------------------------------------------------------------
__global__ __launch_bounds__(NTHREADS, 1)
void pwd_gemm_kernel(float* __restrict__ out) {
    extern __shared__ uint32_t dsm[];
    uint32_t* sA  = dsm;                       // 256 * 68 words
    uint32_t* sB0 = dsm + TM * SW;             // 128 * 68 words
    uint32_t* sB1 = sB0 + TN * SW;             // 128 * 68 words
    float* s_sxRow = (float*)(sB1 + TN * SW);  // 256 floats
    float* s_syCol = s_sxRow + TM;             // 3 * 128 floats (ring)
    uint32_t smu = smem_to_u32(dsm);

    int tid  = threadIdx.x;
    int lane = tid & 31;
    int w    = tid >> 5;
    int qid  = lane >> 2;   // 0..7
    int qtr  = lane & 3;    // 0..3
    int wm   = w >> 2;      // warp row 0..3 (64 rows each)
    int wn   = w & 3;       // warp col 0..3 (32 cols each)

    int m0     = blockIdx.y * TM;
    int nbase0 = blockIdx.x * (NL * TN);
    int b      = blockIdx.z;

    // chunk map: c16 = chunk col (16B units, 0..15), rq = row quotient
    int c16 = tid & 15;
    int rq  = tid >> 4;     // 0..31

    const uint4* ybf = g_ybf + ((size_t)b * NPOS + m0) * (KPW / 4);
    const uint4* xbf0 = g_xbf + ((size_t)b * NPOS + nbase0) * (KPW / 4);

    // ---- prologue: async-stage A (8 chunks/thr) + B tile 0 (4 chunks/thr) ----
#pragma unroll
    for (int i = 0; i < 8; i++) {
        int m = i * 32 + rq;   // 0..255
        cp_async16(smu + (uint32_t)(m * SW + c16 * 4) * 4, ybf + m * 16 + c16);
    }
    uint32_t sB0u = smu + (uint32_t)(TM * SW) * 4;
    uint32_t sB1u = sB0u + (uint32_t)(TN * SW) * 4;
#pragma unroll
    for (int i = 0; i < 4; i++) {
        int n = i * 32 + rq;   // 0..127
        cp_async16(sB0u + (uint32_t)(n * SW + c16 * 4) * 4, xbf0 + n * 16 + c16);
    }
    CP_ASYNC_COMMIT();

    if (tid < TM) {
        s_sxRow[tid] = g_sx[b * NPOS + m0 + tid];
    } else if (tid < TM + TN) {
        s_syCol[tid - TM] = g_sy[b * NPOS + nbase0 + (tid - TM)];
    }
    CP_ASYNC_WAIT_ALL();
    __syncthreads();

    const uint32_t* pA = sA + (wm * 64 + qid) * SW + qtr;

    // ---- tile loop ----
    for (int t = 0; t < NL; t++) {
        int n0 = nbase0 + t * TN;
        const uint32_t* pB = ((t & 1) ? sB1 : sB0) + (wn * 32 + qid) * SW + qtr;

        // issue next tile's B staging (register-free) + syCol slot t+1
        if (t < NL - 1) {
            uint32_t dstu = (t & 1) ? sB0u : sB1u;
            const uint4* xbfn = g_xbf + ((size_t)b * NPOS + n0 + TN) * (KPW / 4);
#pragma unroll
            for (int i = 0; i < 4; i++) {
                int n = i * 32 + rq;
                cp_async16(dstu + (uint32_t)(n * SW + c16 * 4) * 4, xbfn + n * 16 + c16);
            }
            CP_ASYNC_COMMIT();
            if (tid >= TM && tid < TM + TN) {
                s_syCol[(t + 1) * TN + (tid - TM)] = g_sy[b * NPOS + (n0 + TN) + (tid - TM)];
            }
        }

        float acc[4][4][4];
#pragma unroll
        for (int mi = 0; mi < 4; mi++)
#pragma unroll
            for (int j = 0; j < 4; j++)
#pragma unroll
                for (int r = 0; r < 4; r++) acc[mi][j][r] = 0.f;

        // main loop: 8 k-steps of K=16; 24 LDS + 16 MMA per step
#pragma unroll
        for (int s = 0; s < 8; s++) {
            uint32_t af[4][4];
#pragma unroll
            for (int mi = 0; mi < 4; mi++) {
                af[mi][0] = pA[(mi * 16 + 0) * SW + s * 8];
                af[mi][1] = pA[(mi * 16 + 8) * SW + s * 8];
                af[mi][2] = pA[(mi * 16 + 0) * SW + s * 8 + 4];
                af[mi][3] = pA[(mi * 16 + 8) * SW + s * 8 + 4];
            }
#pragma unroll
            for (int j = 0; j < 4; j++) {
                uint32_t b0 = pB[j * 8 * SW + s * 8];
                uint32_t b1 = pB[j * 8 * SW + s * 8 + 4];
#pragma unroll
                for (int mi = 0; mi < 4; mi++) {
                    mma_bf16(acc[mi][j][0], acc[mi][j][1], acc[mi][j][2], acc[mi][j][3],
                             af[mi][0], af[mi][1], af[mi][2], af[mi][3], b0, b1);
                }
            }
        }

        // fused epilogue: P = sx[i] + sy[j] - 2*acc, float2 stores
        const float* syCur = s_syCol + t * TN;
#pragma unroll
        for (int mi = 0; mi < 4; mi++) {
#pragma unroll
            for (int h = 0; h < 2; h++) {
                int r = wm * 64 + mi * 16 + h * 8 + qid;
                float sxv = s_sxRow[r];
                size_t rowOff = ((size_t)b * NPOS + m0 + r) * (size_t)NPOS + n0;
#pragma unroll
                for (int j = 0; j < 4; j++) {
                    int cb = wn * 32 + 8 * j + 2 * qtr;
                    float d0 = acc[mi][j][h * 2 + 0];
                    float d1 = acc[mi][j][h * 2 + 1];
                    float2 v;
                    v.x = syCur[cb + 0] + fmaf(-2.f, d0, sxv);
                    v.y = syCur[cb + 1] + fmaf(-2.f, d1, sxv);
                    *reinterpret_cast<float2*>(out + rowOff + cb) = v;
                }
            }
        }

        if (t < NL - 1) {
            CP_ASYNC_WAIT_ALL();   // B(t+1) landed (issued ~11 kcyc ago)
            __syncthreads();       // all warps done with sBc(t) + B(t+1) visible
        }
    }
}

// ---------------------------------------------------------------------------
// Launch
// ---------------------------------------------------------------------------
extern "C" void kernel_launch(void* const* d_in, const int* in_sizes, int n_in,
                              void* d_out, int out_size) {
    const float* x = (const float*)d_in[0];
    const float* y = (const float*)d_in[1];
    float* out = (float*)d_out;

    // Kernel 1: norms + bf16 transpose-convert (SMEM tile transpose)
    dim3 g1(NPOS / TPOS, BATCH);
    pwd_norms_kernel<<<g1, 256>>>(x, y);

    // Kernel 2: tiled bf16 GEMM, cp.async staging, fused epilogue
    int smemBytes = (TM * SW + 2 * TN * SW + TM + 3 * TN) * 4;   // ~139 KB
    cudaFuncSetAttribute(pwd_gemm_kernel,
                         cudaFuncAttributeMaxDynamicSharedMemorySize, smemBytes);
    dim3 grid(MT_NS, MT_M, BATCH);
    pwd_gemm_kernel<<<grid, NTHREADS, smemBytes>>>(out);
}